// round 7
// baseline (speedup 1.0000x reference)
#include <cuda_runtime.h>
#include <cuda_bf16.h>
#include <cstdint>

#define CLAMP_MIN 1e-12f
#define CLAMP_MAX 1e12f

// Pre-normalized centers scratch (C <= 256, D = 256)
__device__ float g_cnorm[256 * 256];

// Prep: zero the output and write normalized centers (one warp per center row).
__global__ void prep_kernel(const float* __restrict__ centers, float* __restrict__ out, int C) {
    if (blockIdx.x == 0 && threadIdx.x == 0) out[0] = 0.0f;

    const int warp = (blockIdx.x * blockDim.x + threadIdx.x) >> 5;
    const int lane = threadIdx.x & 31;
    if (warp >= C) return;

    const float4* __restrict__ cr = reinterpret_cast<const float4*>(centers) + (size_t)warp * 64;
    float4 b0 = cr[lane];
    float4 b1 = cr[32 + lane];

    float s = 0.0f;
    s = fmaf(b0.x, b0.x, s); s = fmaf(b0.y, b0.y, s);
    s = fmaf(b0.z, b0.z, s); s = fmaf(b0.w, b0.w, s);
    s = fmaf(b1.x, b1.x, s); s = fmaf(b1.y, b1.y, s);
    s = fmaf(b1.z, b1.z, s); s = fmaf(b1.w, b1.w, s);

    #pragma unroll
    for (int off = 16; off > 0; off >>= 1)
        s += __shfl_xor_sync(0xFFFFFFFFu, s, off);

    const float inv = rsqrtf(fmaxf(s, 1e-24f));
    b0.x *= inv; b0.y *= inv; b0.z *= inv; b0.w *= inv;
    b1.x *= inv; b1.y *= inv; b1.z *= inv; b1.w *= inv;

    float4* __restrict__ dst = reinterpret_cast<float4*>(g_cnorm) + (size_t)warp * 64;
    dst[lane]      = b0;
    dst[32 + lane] = b1;
}

__device__ __forceinline__ void cp_async16(uint32_t smem_addr, const void* gptr) {
    asm volatile("cp.async.cg.shared.global [%0], [%1], 16;\n"
                 :: "r"(smem_addr), "l"(gptr) : "memory");
}
__device__ __forceinline__ void cp_commit() {
    asm volatile("cp.async.commit_group;\n" ::: "memory");
}
__device__ __forceinline__ void cp_wait1() {
    asm volatile("cp.async.wait_group 1;\n" ::: "memory");
}

// Main: warp-per-row over a contiguous per-warp chunk (K <= 32 rows).
// Labels preloaded once per chunk (one coalesced LDG, shfl broadcast).
// Emb rows streamed via cp.async into a 3-deep 1KB SMEM ring per warp.
// 1024 thr x 2 blocks/SM = 64 warps/SM; regs ~30.
__global__ __launch_bounds__(1024, 2)
void inner_cos_kernel(const float* __restrict__ ref_emb,
                      const int*   __restrict__ ref_label,
                      float* __restrict__ out,
                      int N, int K, float inv_n) {
    extern __shared__ float4 sbuf[];   // 32 warps * 3 bufs * 64 float4
    __shared__ float ssum[32];

    const int lane = threadIdx.x & 31;
    const int wid  = threadIdx.x >> 5;
    const int warps_per_block = blockDim.x >> 5;
    const int gwarp = blockIdx.x * warps_per_block + wid;

    float4* __restrict__ wbuf = sbuf + wid * 192;   // 3 x 64 float4
    const uint32_t wbuf_s = (uint32_t)__cvta_generic_to_shared(wbuf);

    const int start = gwarp * K;
    const int end   = min(start + K, N);

    float acc = 0.0f;   // meaningful on lane 0

    if (start < end) {
        // Preload this chunk's labels: one coalesced LDG, lane i holds label[start+i].
        const int mylab = __ldg(&ref_label[min(start + lane, N - 1)]);

        const char* __restrict__ embB = reinterpret_cast<const char*>(ref_emb);

        // Prologue: fill rows start, start+1 into bufs 0, 1 (one commit each).
        {
            if (start < end) {
                const char* src = embB + (size_t)start * 1024 + lane * 16;
                cp_async16(wbuf_s + lane * 16, src);
                cp_async16(wbuf_s + 512 + lane * 16, src + 512);
            }
            cp_commit();
            if (start + 1 < end) {
                const char* src = embB + (size_t)(start + 1) * 1024 + lane * 16;
                cp_async16(wbuf_s + 1024 + lane * 16, src);
                cp_async16(wbuf_s + 1536 + lane * 16, src + 512);
            }
            cp_commit();
        }

        for (int i = start; i < end; ++i) {
            // Row i's group is the oldest of the <=2 pending: wait until <=1 pending.
            cp_wait1();
            __syncwarp();

            const int b = (i - start) % 3;
            const float4 a0 = wbuf[b * 64 + lane];
            const float4 a1 = wbuf[b * 64 + 32 + lane];

            const int lab = __shfl_sync(0xFFFFFFFFu, mylab, i - start);
            const float4* __restrict__ cr = reinterpret_cast<const float4*>(g_cnorm) + (size_t)lab * 64;
            const float4 b0 = __ldg(&cr[lane]);
            const float4 b1 = __ldg(&cr[32 + lane]);

            float dot = 0.0f, nx2 = 0.0f;
            dot = fmaf(a0.x, b0.x, dot); dot = fmaf(a0.y, b0.y, dot);
            dot = fmaf(a0.z, b0.z, dot); dot = fmaf(a0.w, b0.w, dot);
            dot = fmaf(a1.x, b1.x, dot); dot = fmaf(a1.y, b1.y, dot);
            dot = fmaf(a1.z, b1.z, dot); dot = fmaf(a1.w, b1.w, dot);
            nx2 = fmaf(a0.x, a0.x, nx2); nx2 = fmaf(a0.y, a0.y, nx2);
            nx2 = fmaf(a0.z, a0.z, nx2); nx2 = fmaf(a0.w, a0.w, nx2);
            nx2 = fmaf(a1.x, a1.x, nx2); nx2 = fmaf(a1.y, a1.y, nx2);
            nx2 = fmaf(a1.z, a1.z, nx2); nx2 = fmaf(a1.w, a1.w, nx2);

            // Split reduction: xor16 both, half-warps finish one value each.
            dot += __shfl_xor_sync(0xFFFFFFFFu, dot, 16);
            nx2 += __shfl_xor_sync(0xFFFFFFFFu, nx2, 16);
            float w = (lane < 16) ? dot : nx2;
            w += __shfl_xor_sync(0xFFFFFFFFu, w, 8);
            w += __shfl_xor_sync(0xFFFFFFFFu, w, 4);
            w += __shfl_xor_sync(0xFFFFFFFFu, w, 2);
            w += __shfl_xor_sync(0xFFFFFFFFu, w, 1);
            const float nxv = __shfl_xor_sync(0xFFFFFFFFu, w, 16);

            if (lane == 0) {
                float cd = 1.0f - w * rsqrtf(fmaxf(nxv, 1e-16f));
                cd = fminf(fmaxf(cd, CLAMP_MIN), CLAMP_MAX);
                acc += cd;
            }

            // Fill row i+2 into buf (i+2)%3 (read finished at iter i-1).
            if (i + 2 < end) {
                const int fb = (i + 2 - start) % 3;
                const char* src = embB + (size_t)(i + 2) * 1024 + lane * 16;
                cp_async16(wbuf_s + fb * 1024 + lane * 16, src);
                cp_async16(wbuf_s + fb * 1024 + 512 + lane * 16, src + 512);
            }
            cp_commit();   // always commit so group counting stays exact
        }
    }

    if (lane == 0) ssum[wid] = acc;
    __syncthreads();

    if (wid == 0) {
        float v = (lane < warps_per_block) ? ssum[lane] : 0.0f;
        #pragma unroll
        for (int off = 16; off > 0; off >>= 1)
            v += __shfl_xor_sync(0xFFFFFFFFu, v, off);
        if (lane == 0)
            atomicAdd(out, v * inv_n);
    }
}

extern "C" void kernel_launch(void* const* d_in, const int* in_sizes, int n_in,
                              void* d_out, int out_size) {
    const float* ref_emb   = (const float*)d_in[0];
    const int*   ref_label = (const int*)d_in[1];
    const float* centers   = (const float*)d_in[2];
    float* out = (float*)d_out;

    const int N = in_sizes[1];
    const int C = in_sizes[2] / 256;     // D = 256
    const float inv_n = 1.0f / (float)N;

    const int prep_threads = 512;
    const int prep_blocks = (C * 32 + prep_threads - 1) / prep_threads;
    prep_kernel<<<prep_blocks, prep_threads>>>(centers, out, C);

    const int threads = 1024;            // 32 warps/block
    const int blocks  = 148 * 2;         // 64 warps/SM
    const int total_warps = blocks * (threads / 32);
    int K = (N + total_warps - 1) / total_warps;   // rows per warp (28 for N=262144)
    if (K > 32) K = 32;                  // label preload holds 32; larger N => multiple waves of chunks
    // If K was clamped, some rows would be uncovered; grow blocks instead.
    int eff_blocks = blocks;
    {
        long long covered = (long long)eff_blocks * (threads / 32) * K;
        while (covered < N) { eff_blocks += 148; covered = (long long)eff_blocks * (threads / 32) * K; }
    }

    const int smem_bytes = 32 * 3 * 1024;   // 96 KB ring buffers
    static int attr_set = 0;
    cudaFuncSetAttribute(inner_cos_kernel, cudaFuncAttributeMaxDynamicSharedMemorySize, smem_bytes);
    (void)attr_set;

    inner_cos_kernel<<<eff_blocks, threads, smem_bytes>>>(ref_emb, ref_label, out, N, K, inv_n);
}

// round 8
// speedup vs baseline: 1.1187x; 1.1187x over previous
#include <cuda_runtime.h>
#include <cuda_bf16.h>
#include <cstdint>

#define CLAMP_MIN 1e-12f
#define CLAMP_MAX 1e12f

// Pre-normalized centers scratch (C <= 256, D = 256)
__device__ float g_cnorm[256 * 256];

// Prep: zero the output and write normalized centers (one warp per center row).
__global__ void prep_kernel(const float* __restrict__ centers, float* __restrict__ out, int C) {
    if (blockIdx.x == 0 && threadIdx.x == 0) out[0] = 0.0f;

    const int warp = (blockIdx.x * blockDim.x + threadIdx.x) >> 5;
    const int lane = threadIdx.x & 31;
    if (warp >= C) return;

    const float4* __restrict__ cr = reinterpret_cast<const float4*>(centers) + (size_t)warp * 64;
    float4 b0 = cr[lane];
    float4 b1 = cr[32 + lane];

    float s = 0.0f;
    s = fmaf(b0.x, b0.x, s); s = fmaf(b0.y, b0.y, s);
    s = fmaf(b0.z, b0.z, s); s = fmaf(b0.w, b0.w, s);
    s = fmaf(b1.x, b1.x, s); s = fmaf(b1.y, b1.y, s);
    s = fmaf(b1.z, b1.z, s); s = fmaf(b1.w, b1.w, s);

    #pragma unroll
    for (int off = 16; off > 0; off >>= 1)
        s += __shfl_xor_sync(0xFFFFFFFFu, s, off);

    const float inv = rsqrtf(fmaxf(s, 1e-24f));
    b0.x *= inv; b0.y *= inv; b0.z *= inv; b0.w *= inv;
    b1.x *= inv; b1.y *= inv; b1.z *= inv; b1.w *= inv;

    float4* __restrict__ dst = reinterpret_cast<float4*>(g_cnorm) + (size_t)warp * 64;
    dst[lane]      = b0;
    dst[32 + lane] = b1;
}

// Packed dual-FMA: d = a*b + d on two f32 lanes (Blackwell f32x2 pipe).
__device__ __forceinline__ void fma2(unsigned long long& d,
                                     unsigned long long a,
                                     unsigned long long b) {
    asm("fma.rn.f32x2 %0, %1, %2, %0;" : "+l"(d) : "l"(a), "l"(b));
}
__device__ __forceinline__ float pair_sum(unsigned long long v) {
    unsigned int lo, hi;
    asm("mov.b64 {%0, %1}, %2;" : "=r"(lo), "=r"(hi) : "l"(v));
    return __uint_as_float(lo) + __uint_as_float(hi);
}

// Main: persistent grid, warp-per-row grid-stride (R4 structure),
// + next-label prefetch + packed f32x2 FMAs. <=32 regs, 64 warps/SM.
__global__ __launch_bounds__(1024, 2)
void inner_cos_kernel(const float* __restrict__ ref_emb,
                      const int*   __restrict__ ref_label,
                      float* __restrict__ out,
                      int N, float inv_n) {
    const int lane = threadIdx.x & 31;
    const int wid  = threadIdx.x >> 5;
    const int warps_per_block = blockDim.x >> 5;
    const int gwarp = blockIdx.x * warps_per_block + wid;
    const int total_warps = gridDim.x * warps_per_block;

    __shared__ float ssum[32];

    typedef unsigned long long u64;
    const ulonglong2* __restrict__ emb2 = reinterpret_cast<const ulonglong2*>(ref_emb);
    // row stride in ulonglong2 units: 1024B / 16B = 64

    float acc = 0.0f;   // meaningful on lane 0

    if (gwarp < N) {
        int lab = __ldg(&ref_label[gwarp]);   // prologue label

        for (int row = gwarp; row < N; row += total_warps) {
            // Prefetch next iteration's label (off the critical path).
            const int nlab = __ldg(&ref_label[min(row + total_warps, N - 1)]);

            const longlong2* xr = reinterpret_cast<const longlong2*>(emb2 + (size_t)row * 64 + lane);
            const longlong2* cr = reinterpret_cast<const longlong2*>(
                reinterpret_cast<const ulonglong2*>(g_cnorm) + (size_t)lab * 64 + lane);

            longlong2 ea0 = __ldcs(xr);
            longlong2 ea1 = __ldcs(xr + 32);
            longlong2 cb0 = __ldg(cr);
            longlong2 cb1 = __ldg(cr + 32);

            u64 dotp = 0ull, nxp = 0ull;   // packed (0.0f, 0.0f)
            fma2(dotp, (u64)ea0.x, (u64)cb0.x);
            fma2(dotp, (u64)ea0.y, (u64)cb0.y);
            fma2(dotp, (u64)ea1.x, (u64)cb1.x);
            fma2(dotp, (u64)ea1.y, (u64)cb1.y);
            fma2(nxp,  (u64)ea0.x, (u64)ea0.x);
            fma2(nxp,  (u64)ea0.y, (u64)ea0.y);
            fma2(nxp,  (u64)ea1.x, (u64)ea1.x);
            fma2(nxp,  (u64)ea1.y, (u64)ea1.y);

            float dot = pair_sum(dotp);
            float nx2 = pair_sum(nxp);

            // Split reduction: xor16 both, half-warps finish one value each.
            dot += __shfl_xor_sync(0xFFFFFFFFu, dot, 16);
            nx2 += __shfl_xor_sync(0xFFFFFFFFu, nx2, 16);
            float w = (lane < 16) ? dot : nx2;
            w += __shfl_xor_sync(0xFFFFFFFFu, w, 8);
            w += __shfl_xor_sync(0xFFFFFFFFu, w, 4);
            w += __shfl_xor_sync(0xFFFFFFFFu, w, 2);
            w += __shfl_xor_sync(0xFFFFFFFFu, w, 1);
            const float nxv = __shfl_xor_sync(0xFFFFFFFFu, w, 16);

            if (lane == 0) {
                float cd = 1.0f - w * rsqrtf(fmaxf(nxv, 1e-16f));
                cd = fminf(fmaxf(cd, CLAMP_MIN), CLAMP_MAX);
                acc += cd;
            }

            lab = nlab;
        }
    }

    if (lane == 0) ssum[wid] = acc;
    __syncthreads();

    if (wid == 0) {
        float v = (lane < warps_per_block) ? ssum[lane] : 0.0f;
        #pragma unroll
        for (int off = 16; off > 0; off >>= 1)
            v += __shfl_xor_sync(0xFFFFFFFFu, v, off);
        if (lane == 0)
            atomicAdd(out, v * inv_n);
    }
}

extern "C" void kernel_launch(void* const* d_in, const int* in_sizes, int n_in,
                              void* d_out, int out_size) {
    const float* ref_emb   = (const float*)d_in[0];
    const int*   ref_label = (const int*)d_in[1];
    const float* centers   = (const float*)d_in[2];
    float* out = (float*)d_out;

    const int N = in_sizes[1];
    const int C = in_sizes[2] / 256;     // D = 256
    const float inv_n = 1.0f / (float)N;

    const int prep_threads = 512;
    const int prep_blocks = (C * 32 + prep_threads - 1) / prep_threads;
    prep_kernel<<<prep_blocks, prep_threads>>>(centers, out, C);

    const int threads = 1024;            // 32 warps/block
    const int blocks  = 148 * 2;         // persistent single wave, 64 warps/SM
    inner_cos_kernel<<<blocks, threads>>>(ref_emb, ref_label, out, N, inv_n);
}